// round 1
// baseline (speedup 1.0000x reference)
#include <cuda_runtime.h>
#include <cuda_bf16.h>

// GridSample bilinear, zeros padding, align_corners=True.
// x: [N=8, C=64, H=256, W=256] fp32 ; grid: [N, 256, 256, 2] fp32 (dx,dy pixel offsets)
// out: [N, C, 256, 256] fp32
//
// One thread per spatial position (n, ho, wo): compute corner indices + weights
// once, loop over 64 channels. Stores coalesced (wo contiguous within warp).

#define GS_N 8
#define GS_C 64
#define GS_H 256
#define GS_W 256

__global__ void __launch_bounds__(256) gridsample_kernel(
    const float* __restrict__ x,
    const float* __restrict__ grid,
    float* __restrict__ out)
{
    const int idx = blockIdx.x * blockDim.x + threadIdx.x;   // over N*H*W
    const int total = GS_N * GS_H * GS_W;
    if (idx >= total) return;

    const int wo = idx & (GS_W - 1);
    const int ho = (idx >> 8) & (GS_H - 1);
    const int n  = idx >> 16;

    // grid read: coalesced float2
    const float2 g = reinterpret_cast<const float2*>(grid)[idx];

    // Replicate reference chain exactly (it cancels mathematically, but match
    // rounding as closely as possible).
    const float abs_x = g.x + (float)wo;
    const float abs_y = g.y + (float)ho;
    const float norm_x = abs_x * 2.0f / (float)(GS_W - 1) - 1.0f;
    const float norm_y = abs_y * 2.0f / (float)(GS_H - 1) - 1.0f;
    const float ix = (norm_x + 1.0f) * 0.5f * (float)(GS_W - 1);
    const float iy = (norm_y + 1.0f) * 0.5f * (float)(GS_H - 1);

    const float x0f = floorf(ix);
    const float y0f = floorf(iy);
    const float wx1 = ix - x0f, wx0 = 1.0f - wx1;
    const float wy1 = iy - y0f, wy0 = 1.0f - wy1;

    const int x0 = (int)x0f, x1 = x0 + 1;
    const int y0 = (int)y0f, y1 = y0 + 1;

    const bool bx0 = (x0 >= 0) & (x0 <= GS_W - 1);
    const bool bx1 = (x1 >= 0) & (x1 <= GS_W - 1);
    const bool by0 = (y0 >= 0) & (y0 <= GS_H - 1);
    const bool by1 = (y1 >= 0) & (y1 <= GS_H - 1);

    // zeros padding: zero the weight of OOB corners
    const float w00 = wy0 * wx0 * (float)(by0 & bx0);
    const float w01 = wy0 * wx1 * (float)(by0 & bx1);
    const float w10 = wy1 * wx0 * (float)(by1 & bx0);
    const float w11 = wy1 * wx1 * (float)(by1 & bx1);

    const int cx0 = min(max(x0, 0), GS_W - 1);
    const int cx1 = min(max(x1, 0), GS_W - 1);
    const int cy0 = min(max(y0, 0), GS_H - 1);
    const int cy1 = min(max(y1, 0), GS_H - 1);

    const int o00 = cy0 * GS_W + cx0;
    const int o01 = cy0 * GS_W + cx1;
    const int o10 = cy1 * GS_W + cx0;
    const int o11 = cy1 * GS_W + cx1;

    const long long plane  = (long long)GS_H * GS_W;          // 65536
    const long long nbase  = (long long)n * GS_C * plane;
    const long long obase  = nbase + (long long)ho * GS_W + wo;

    const float* __restrict__ xp = x + nbase;
    float* __restrict__ op = out + obase;

    #pragma unroll 8
    for (int c = 0; c < GS_C; ++c) {
        const float* p = xp + (long long)c * plane;
        float v = p[o00] * w00 + p[o01] * w01 + p[o10] * w10 + p[o11] * w11;
        op[(long long)c * plane] = v;
    }
}

extern "C" void kernel_launch(void* const* d_in, const int* in_sizes, int n_in,
                              void* d_out, int out_size)
{
    const float* x    = (const float*)d_in[0];
    const float* grid = (const float*)d_in[1];
    float* out        = (float*)d_out;

    const int total = GS_N * GS_H * GS_W;     // 524288 spatial positions
    const int threads = 256;
    const int blocks = (total + threads - 1) / threads;   // 2048
    gridsample_kernel<<<blocks, threads>>>(x, grid, out);
}

// round 2
// speedup vs baseline: 1.0260x; 1.0260x over previous
#include <cuda_runtime.h>
#include <cuda_bf16.h>

// GridSample bilinear, zeros padding, align_corners=True.
// x: [8, 64, 256, 256] fp32 ; grid: [8, 256, 256, 2] fp32 (dx,dy pixel offsets)
// out: [8, 64, 256, 256] fp32
//
// One thread per spatial position; weights/indices computed once, reused
// across 64 channels. All indexing 32-bit (total elems 33.5M < 2^31).
// __launch_bounds__(256, 8) -> 32 regs -> 100% occupancy to saturate L1tex.

#define GS_N 8
#define GS_C 64
#define GS_H 256
#define GS_W 256
#define GS_PLANE (GS_H * GS_W)   // 65536

__global__ void __launch_bounds__(256, 8) gridsample_kernel(
    const float* __restrict__ x,
    const float* __restrict__ grid,
    float* __restrict__ out)
{
    const int idx = blockIdx.x * blockDim.x + threadIdx.x;   // over N*H*W

    const int wo = idx & (GS_W - 1);
    const int ho = (idx >> 8) & (GS_H - 1);
    const int n  = idx >> 16;

    // grid read: coalesced float2
    const float2 g = __ldg(reinterpret_cast<const float2*>(grid) + idx);

    // Replicate reference chain exactly for rounding fidelity.
    const float abs_x = g.x + (float)wo;
    const float abs_y = g.y + (float)ho;
    const float norm_x = abs_x * 2.0f / (float)(GS_W - 1) - 1.0f;
    const float norm_y = abs_y * 2.0f / (float)(GS_H - 1) - 1.0f;
    const float ix = (norm_x + 1.0f) * 0.5f * (float)(GS_W - 1);
    const float iy = (norm_y + 1.0f) * 0.5f * (float)(GS_H - 1);

    const float x0f = floorf(ix);
    const float y0f = floorf(iy);
    const float wx1 = ix - x0f, wx0 = 1.0f - wx1;
    const float wy1 = iy - y0f, wy0 = 1.0f - wy1;

    const int x0 = (int)x0f, x1 = x0 + 1;
    const int y0 = (int)y0f, y1 = y0 + 1;

    const bool bx0 = (x0 >= 0) & (x0 <= GS_W - 1);
    const bool bx1 = (x1 >= 0) & (x1 <= GS_W - 1);
    const bool by0 = (y0 >= 0) & (y0 <= GS_H - 1);
    const bool by1 = (y1 >= 0) & (y1 <= GS_H - 1);

    // zeros padding: zero the weight of OOB corners
    const float w00 = wy0 * wx0 * (float)(by0 & bx0);
    const float w01 = wy0 * wx1 * (float)(by0 & bx1);
    const float w10 = wy1 * wx0 * (float)(by1 & bx0);
    const float w11 = wy1 * wx1 * (float)(by1 & bx1);

    const int cx0 = min(max(x0, 0), GS_W - 1);
    const int cx1 = min(max(x1, 0), GS_W - 1);
    const int cy0 = min(max(y0, 0), GS_H - 1);
    const int cy1 = min(max(y1, 0), GS_H - 1);

    const int o00 = cy0 * GS_W + cx0;
    const int o01 = cy0 * GS_W + cx1;
    const int o10 = cy1 * GS_W + cx0;
    const int o11 = cy1 * GS_W + cx1;

    // 32-bit indexing throughout (fits easily in 2^31)
    const int nbase = n * (GS_C * GS_PLANE);
    const int obase = nbase + ho * GS_W + wo;

    const float* __restrict__ xp = x + nbase;
    float* __restrict__ op = out + obase;

    #pragma unroll 4
    for (int c = 0; c < GS_C; ++c) {
        const float* p = xp + c * GS_PLANE;
        float v = __ldg(p + o00) * w00 + __ldg(p + o01) * w01
                + __ldg(p + o10) * w10 + __ldg(p + o11) * w11;
        op[c * GS_PLANE] = v;
    }
}

extern "C" void kernel_launch(void* const* d_in, const int* in_sizes, int n_in,
                              void* d_out, int out_size)
{
    const float* x    = (const float*)d_in[0];
    const float* grid = (const float*)d_in[1];
    float* out        = (float*)d_out;

    const int total = GS_N * GS_H * GS_W;     // 524288 spatial positions
    const int threads = 256;
    const int blocks = total / threads;       // 2048 (exact)
    gridsample_kernel<<<blocks, threads>>>(x, grid, out);
}